// round 1
// baseline (speedup 1.0000x reference)
#include <cuda_runtime.h>
#include <cuda_bf16.h>
#include <cstddef>

#define NDIM 4096
#define BM 128
#define BN 128
#define BK 8

// ---------------- device scratch (no allocations allowed) ----------------
__device__ float g_X[(size_t)NDIM * NDIM];
__device__ float g_A[(size_t)NDIM * NDIM];
__device__ float g_B[(size_t)NDIM * NDIM];
__device__ float g_v[NDIM];
__device__ float g_w[NDIM];
__device__ float g_u[NDIM];
__device__ float g_scal[4];

// ---------------- small kernels: power iteration ----------------
__global__ void om_init_v(float* v) {
    int i = blockIdx.x * blockDim.x + threadIdx.x;
    if (i < NDIM) v[i] = 1.0f;
}

// w = H v  (one block per row, coalesced row reads)
__global__ void om_matvec(const float* __restrict__ H, const float* __restrict__ v,
                          float* __restrict__ w) {
    int row = blockIdx.x;
    const float* hr = H + (size_t)row * NDIM;
    float acc = 0.0f;
    for (int j = threadIdx.x; j < NDIM; j += 256) acc += hr[j] * v[j];
    __shared__ float red[256];
    red[threadIdx.x] = acc;
    __syncthreads();
    for (int s = 128; s > 0; s >>= 1) {
        if (threadIdx.x < s) red[threadIdx.x] += red[threadIdx.x + s];
        __syncthreads();
    }
    if (threadIdx.x == 0) w[row] = red[0];
}

__global__ void om_zero_u(float* u) {
    int i = blockIdx.x * blockDim.x + threadIdx.x;
    if (i < NDIM) u[i] = 0.0f;
}

// u += H^T w   (grid (32,32), block 128: coalesced column-stripe reads)
__global__ void om_matvecT(const float* __restrict__ H, const float* __restrict__ w,
                           float* __restrict__ u) {
    int col = blockIdx.x * 128 + threadIdx.x;
    int i0 = blockIdx.y * 128;
    float acc = 0.0f;
    #pragma unroll 4
    for (int i = i0; i < i0 + 128; i++) acc += H[(size_t)i * NDIM + col] * w[i];
    atomicAdd(&u[col], acc);
}

// scal[0] = ||u||^2  (single block)
__global__ void om_normsq(const float* __restrict__ u, float* scal) {
    __shared__ float red[1024];
    float acc = 0.0f;
    for (int i = threadIdx.x; i < NDIM; i += 1024) { float x = u[i]; acc += x * x; }
    red[threadIdx.x] = acc;
    __syncthreads();
    for (int s = 512; s > 0; s >>= 1) {
        if (threadIdx.x < s) red[threadIdx.x] += red[threadIdx.x + s];
        __syncthreads();
    }
    if (threadIdx.x == 0) scal[0] = red[0];
}

__global__ void om_normalize(const float* __restrict__ u, const float* __restrict__ scal,
                             float* __restrict__ v) {
    int i = blockIdx.x * blockDim.x + threadIdx.x;
    if (i < NDIM) v[i] = u[i] * rsqrtf(scal[0]);
}

// sigma_hat = (||u||^2)^{1/4}; scal[1] = 1/(1.06*sigma_hat)
__global__ void om_compute_scale(float* scal) {
    scal[1] = 1.0f / (1.06f * sqrtf(sqrtf(scal[0])));
}

// X = H * scal[1]
__global__ void om_scale_init(const float* __restrict__ H, const float* __restrict__ scal,
                              float* __restrict__ X) {
    size_t i = (size_t)blockIdx.x * blockDim.x + threadIdx.x;
    float s = scal[1];
    if (i < (size_t)NDIM * NDIM) X[i] = H[i] * s;
}

// ---------------- GEMM: D = alpha * op(P) * Q + beta * R ----------------
// op(P) = P^T if TRANSP else P. All matrices NDIM x NDIM row-major fp32.
template <bool TRANSP>
__global__ void __launch_bounds__(256)
om_gemm(const float* __restrict__ P, const float* __restrict__ Q,
        const float* __restrict__ R, float* __restrict__ D,
        float alpha, float beta) {
    __shared__ float As[BK][BM];
    __shared__ float Bs[BK][BN];

    const int bm = blockIdx.y * BM;
    const int bn = blockIdx.x * BN;
    const int tid = threadIdx.x;
    const int tx = tid & 15;   // n direction (16)
    const int ty = tid >> 4;   // m direction (16)

    float acc[8][8];
    #pragma unroll
    for (int i = 0; i < 8; i++)
        #pragma unroll
        for (int j = 0; j < 8; j++) acc[i][j] = 0.0f;

    for (int k0 = 0; k0 < NDIM; k0 += BK) {
        // ---- load op(P) tile into As[k][m] ----
        if (!TRANSP) {
            int m = tid >> 1;
            int k = (tid & 1) * 4;
            float4 a = *(const float4*)&P[(size_t)(bm + m) * NDIM + k0 + k];
            As[k + 0][m] = a.x;
            As[k + 1][m] = a.y;
            As[k + 2][m] = a.z;
            As[k + 3][m] = a.w;
        } else {
            int k = tid >> 5;
            int m = (tid & 31) * 4;
            float4 a = *(const float4*)&P[(size_t)(k0 + k) * NDIM + bm + m];
            *(float4*)&As[k][m] = a;
        }
        // ---- load Q tile into Bs[k][n] ----
        {
            int k = tid >> 5;
            int n = (tid & 31) * 4;
            float4 b = *(const float4*)&Q[(size_t)(k0 + k) * NDIM + bn + n];
            *(float4*)&Bs[k][n] = b;
        }
        __syncthreads();

        #pragma unroll
        for (int k = 0; k < BK; k++) {
            float rm[8], rn[8];
            #pragma unroll
            for (int i = 0; i < 8; i++) rm[i] = As[k][ty * 8 + i];
            #pragma unroll
            for (int j = 0; j < 8; j++) rn[j] = Bs[k][tx * 8 + j];
            #pragma unroll
            for (int i = 0; i < 8; i++)
                #pragma unroll
                for (int j = 0; j < 8; j++) acc[i][j] += rm[i] * rn[j];
        }
        __syncthreads();
    }

    #pragma unroll
    for (int i = 0; i < 8; i++) {
        int row = bm + ty * 8 + i;
        #pragma unroll
        for (int j = 0; j < 8; j += 4) {
            int col = bn + tx * 8 + j;
            size_t idx = (size_t)row * NDIM + col;
            float4 r = *(const float4*)&R[idx];
            float4 d;
            d.x = alpha * acc[i][j + 0] + beta * r.x;
            d.y = alpha * acc[i][j + 1] + beta * r.y;
            d.z = alpha * acc[i][j + 2] + beta * r.z;
            d.w = alpha * acc[i][j + 3] + beta * r.w;
            *(float4*)&D[idx] = d;
        }
    }
}

// ---------------- host orchestration ----------------
extern "C" void kernel_launch(void* const* d_in, const int* in_sizes, int n_in,
                              void* d_out, int out_size) {
    (void)in_sizes; (void)n_in; (void)out_size;
    const float* H = (const float*)d_in[0];

    float *X0, *A, *B, *v, *w, *u, *scal;
    cudaGetSymbolAddress((void**)&X0, g_X);
    cudaGetSymbolAddress((void**)&A, g_A);
    cudaGetSymbolAddress((void**)&B, g_B);
    cudaGetSymbolAddress((void**)&v, g_v);
    cudaGetSymbolAddress((void**)&w, g_w);
    cudaGetSymbolAddress((void**)&u, g_u);
    cudaGetSymbolAddress((void**)&scal, g_scal);

    const dim3 ggrid(NDIM / BN, NDIM / BM);   // (32, 32)
    const dim3 gblk(256);

    // ---- power iteration: sigma_max estimate (lower bound, 30 iters) ----
    om_init_v<<<16, 256>>>(v);
    for (int it = 0; it < 30; it++) {
        om_matvec<<<NDIM, 256>>>(H, v, w);
        om_zero_u<<<16, 256>>>(u);
        om_matvecT<<<dim3(32, 32), 128>>>(H, w, u);
        om_normsq<<<1, 1024>>>(u, scal);
        om_normalize<<<16, 256>>>(u, scal, v);
    }
    om_compute_scale<<<1, 1>>>(scal);

    // ---- X0 = H / (1.06 * sigma_hat) ----
    om_scale_init<<<(NDIM * (NDIM / 256)), 256>>>(H, scal, X0);

    float* Xc = X0;
    float* Xn = (float*)d_out;

    // ---- 11 quintic (Muon) iterations: X <- aX + bX A + cX A^2, A = X^T X ----
    const float qa = 3.4445f, qb = -4.7750f, qc = 2.0315f;
    for (int it = 0; it < 11; it++) {
        om_gemm<true ><<<ggrid, gblk>>>(Xc, Xc, Xc, A, 1.0f, 0.0f);   // A = X^T X
        om_gemm<false><<<ggrid, gblk>>>(A,  A,  A,  B, qc,   qb);     // B = c A^2 + b A
        om_gemm<false><<<ggrid, gblk>>>(Xc, B,  Xc, Xn, 1.0f, qa);    // Xn = X B + a X
        float* t = Xc; Xc = Xn; Xn = t;
    }

    // ---- 6 cubic Newton-Schulz iterations: X <- 1.5X - 0.5 X (X^T X) ----
    for (int it = 0; it < 6; it++) {
        om_gemm<true ><<<ggrid, gblk>>>(Xc, Xc, Xc, A, 1.0f, 0.0f);   // A = X^T X
        om_gemm<false><<<ggrid, gblk>>>(Xc, A,  Xc, Xn, -0.5f, 1.5f); // Xn = 1.5X - 0.5 X A
        float* t = Xc; Xc = Xn; Xn = t;
    }

    if (Xc != (float*)d_out) {
        cudaMemcpyAsync(d_out, Xc, sizeof(float) * (size_t)NDIM * NDIM,
                        cudaMemcpyDeviceToDevice);
    }
}